// round 2
// baseline (speedup 1.0000x reference)
#include <cuda_runtime.h>
#include <math.h>

#define NB 16
#define SDIM 512

// ---------------- persistent scratch (no allocs allowed) ----------------
static __device__ float g_bufA[16777216];   // max: (16,64,128,128)
static __device__ float g_bufB[17040384];   // max: (16,64,129,129)

static __device__ float g_style0[NB * 256];
static __device__ float g_style1[NB * 128];
static __device__ float g_style2[NB * 128];
static __device__ float g_style3[NB * 64];
static __device__ float g_style4[NB * 64];
static __device__ float g_stylef[NB * 32];

static __device__ float g_demod0[NB * 128];
static __device__ float g_demod1[NB * 128];
static __device__ float g_demod2[NB * 64];
static __device__ float g_demod3[NB * 64];
static __device__ float g_demod4[NB * 32];

static __device__ float g_wsq0[128 * 256];
static __device__ float g_wsq1[128 * 128];
static __device__ float g_wsq2[64 * 128];
static __device__ float g_wsq3[64 * 64];
static __device__ float g_wsq4[32 * 64];

__device__ __forceinline__ float* style_ptr(int id) {
    switch (id) {
        case 0: return g_style0;
        case 1: return g_style1;
        case 2: return g_style2;
        case 3: return g_style3;
        case 4: return g_style4;
        default: return g_stylef;
    }
}
__device__ __forceinline__ float* demod_ptr(int id) {
    switch (id) {
        case 0: return g_demod0;
        case 1: return g_demod1;
        case 2: return g_demod2;
        case 3: return g_demod3;
        default: return g_demod4;
    }
}
__device__ __forceinline__ float* wsq_ptr(int id) {
    switch (id) {
        case 0: return g_wsq0;
        case 1: return g_wsq1;
        case 2: return g_wsq2;
        case 3: return g_wsq3;
        default: return g_wsq4;
    }
}

// ---------------- style = z @ mw^T / sqrt(512) + mb ----------------
__global__ void style_kernel(const float* __restrict__ z,
                             const float* __restrict__ mw,
                             const float* __restrict__ mb,
                             int Ci, int style_id) {
    int warp = blockIdx.x * (blockDim.x >> 5) + (threadIdx.x >> 5);
    int lane = threadIdx.x & 31;
    if (warp >= NB * Ci) return;
    int b = warp / Ci;
    int ci = warp - b * Ci;
    const float* zr = z + b * SDIM;
    const float* mr = mw + (size_t)ci * SDIM;
    float s = 0.f;
#pragma unroll 4
    for (int k = lane; k < SDIM; k += 32) s += zr[k] * mr[k];
#pragma unroll
    for (int o = 16; o; o >>= 1) s += __shfl_xor_sync(0xffffffffu, s, o);
    if (lane == 0) style_ptr(style_id)[warp] = s * 0.04419417382415922f + mb[ci];
}

// ---------------- wsq[co,ci] = sum_taps (w^2) / (Ci*9) ----------------
__global__ void wsq_kernel(const float* __restrict__ w, int Co, int Ci, int wsq_id) {
    int i = blockIdx.x * blockDim.x + threadIdx.x;
    if (i >= Co * Ci) return;
    const float* p = w + (size_t)i * 9;
    float s = 0.f;
#pragma unroll
    for (int t = 0; t < 9; t++) s += p[t] * p[t];
    wsq_ptr(wsq_id)[i] = s * (1.0f / (float)(Ci * 9));
}

// ---------------- demod[b,co] = rsqrt(sum_ci style^2 * wsq + 1e-8) ----------------
__global__ void demod_kernel(int style_id, int wsq_id, int demod_id, int Co, int Ci) {
    int warp = blockIdx.x * (blockDim.x >> 5) + (threadIdx.x >> 5);
    int lane = threadIdx.x & 31;
    if (warp >= NB * Co) return;
    int b = warp / Co;
    int co = warp - b * Co;
    const float* st = style_ptr(style_id) + b * Ci;
    const float* wq = wsq_ptr(wsq_id) + (size_t)co * Ci;
    float s = 0.f;
    for (int ci = lane; ci < Ci; ci += 32) {
        float sv = st[ci];
        s += sv * sv * wq[ci];
    }
#pragma unroll
    for (int o = 16; o; o >>= 1) s += __shfl_xor_sync(0xffffffffu, s, o);
    if (lane == 0) demod_ptr(demod_id)[warp] = rsqrtf(s + 1e-8f);
}

// ---------------- compose: bufA = (fg + (1-mask)*bg) * style0 ----------------
__global__ void compose_kernel(const float* __restrict__ fg,
                               const float* __restrict__ mask,
                               const float* __restrict__ bg) {
    int idx = blockIdx.x * blockDim.x + threadIdx.x;  // over 16*256*1024
    int p = idx & 1023;
    int c = (idx >> 10) & 255;
    int b = idx >> 18;
    float m = 1.0f - mask[b * 1024 + p];
    float v = fg[idx] + m * bg[idx];
    g_bufA[idx] = v * g_style0[b * 256 + c];
}

// ---------------- 3x3 conv, pad 1, with styled-conv epilogue ----------------
// epilogue: v = acc*demod + bias; v = leaky(v)*sqrt2*style_next
template <int CIN, int COUT, int H, int W, bool SRC_A>
__global__ __launch_bounds__(256) void conv3x3_kernel(const float* __restrict__ wraw,
                                                      const float* __restrict__ bias,
                                                      int demod_id, int style_id) {
    constexpr int CO_T = 32, CI_T = 8, TH = 8, TW = 32;
    constexpr int IN_LD = 35;   // (TW+2)=34 padded to 35 (conflict-free)
    constexpr int W_LD = 33;    // CO_T+1
    constexpr int TILES_X = W / TW;
    __shared__ float s_in[CI_T][TH + 2][IN_LD];
    __shared__ float s_w[CI_T][9][W_LD];

    const float* in = SRC_A ? g_bufA : g_bufB;
    float* out = SRC_A ? g_bufB : g_bufA;
    const float* demod = demod_ptr(demod_id);
    const float* styn = style_ptr(style_id);

    int tid = threadIdx.x;
    int tile = blockIdx.x;
    int tx0 = (tile % TILES_X) * TW;
    int ty0 = (tile / TILES_X) * TH;
    int co_base = blockIdx.y * CO_T;
    int b = blockIdx.z;

    int co_grp = tid >> 6;        // 0..3 (uniform per warp)
    int pg = tid & 63;
    int r = pg >> 3;              // 0..7
    int c0 = (pg & 7) << 2;       // 0..28

    float acc[8][4];
#pragma unroll
    for (int j = 0; j < 8; j++)
#pragma unroll
        for (int p = 0; p < 4; p++) acc[j][p] = 0.f;

    const float wscale = rsqrtf((float)(CIN * 9));
    const float* in_b = in + (size_t)b * CIN * H * W;

    for (int cb = 0; cb < CIN; cb += CI_T) {
        __syncthreads();
        // input tile (with halo), zero-padded at edges
        for (int idx = tid; idx < CI_T * (TH + 2) * 34; idx += 256) {
            int ci = idx / ((TH + 2) * 34);
            int rem = idx % ((TH + 2) * 34);
            int iy = rem / 34, ix = rem % 34;
            int gy = ty0 + iy - 1, gx = tx0 + ix - 1;
            float v = 0.f;
            if (gy >= 0 && gy < H && gx >= 0 && gx < W)
                v = in_b[(size_t)(cb + ci) * H * W + gy * W + gx];
            s_in[ci][iy][ix] = v;
        }
        // weights (pre-scaled)
        for (int idx = tid; idx < CO_T * CI_T * 9; idx += 256) {
            int co = idx / (CI_T * 9);
            int rem = idx % (CI_T * 9);
            int ci = rem / 9, tap = rem % 9;
            s_w[ci][tap][co] =
                wraw[((size_t)(co_base + co) * CIN + cb + ci) * 9 + tap] * wscale;
        }
        __syncthreads();
#pragma unroll
        for (int ci = 0; ci < CI_T; ci++) {
#pragma unroll
            for (int ky = 0; ky < 3; ky++) {
                float xin[6];
#pragma unroll
                for (int t = 0; t < 6; t++) xin[t] = s_in[ci][r + ky][c0 + t];
#pragma unroll
                for (int kx = 0; kx < 3; kx++) {
#pragma unroll
                    for (int j = 0; j < 8; j++) {
                        float wv = s_w[ci][ky * 3 + kx][co_grp * 8 + j];
#pragma unroll
                        for (int p = 0; p < 4; p++)
                            acc[j][p] = fmaf(wv, xin[kx + p], acc[j][p]);
                    }
                }
            }
        }
    }
    // epilogue
    int oy = ty0 + r;
    float* out_b = out + (size_t)b * COUT * H * W;
#pragma unroll
    for (int j = 0; j < 8; j++) {
        int co = co_base + co_grp * 8 + j;
        float dm = demod[b * COUT + co];
        float bi = bias[co];
        float sn = styn[b * COUT + co];
#pragma unroll
        for (int p = 0; p < 4; p++) {
            float v = acc[j][p] * dm + bi;
            v = (v > 0.f ? v : 0.2f * v) * 1.41421356237309515f * sn;
            out_b[(size_t)co * H * W + oy * W + tx0 + c0 + p] = v;
        }
    }
}

// ---------------- transposed conv (lhs_dilation=2, pad 2, flipped kernel) ----
// out size = 2*HIN+1; epilogue: * demod only (blur+act comes next)
template <int CIN, int COUT, int HIN, bool SRC_A>
__global__ __launch_bounds__(256) void tconv_kernel(const float* __restrict__ wraw,
                                                    int demod_id) {
    constexpr int HOUT = 2 * HIN + 1;
    constexpr int CO_T = 32, CI_T = 8, TH = 8, TW = 32;
    constexpr int IR = 6, ICW = 18, IC_LD = 19;
    constexpr int TILES_X = (HOUT + TW - 1) / TW;
    __shared__ float s_in[CI_T][IR][IC_LD];
    __shared__ float s_w[CI_T][9][CO_T + 1];

    const float* in = SRC_A ? g_bufA : g_bufB;
    float* out = SRC_A ? g_bufB : g_bufA;
    const float* demod = demod_ptr(demod_id);

    int tid = threadIdx.x;
    int tile = blockIdx.x;
    int tx0 = (tile % TILES_X) * TW;
    int ty0 = (tile / TILES_X) * TH;
    int co_base = blockIdx.y * CO_T;
    int b = blockIdx.z;

    int co_grp = tid >> 6;
    int lane = tid & 31;
    int wrp = tid >> 5;
    int r = 2 * ((lane >> 3) & 3) + (wrp & 1);  // row parity uniform per warp
    int c0 = (lane & 7) << 2;
    int h = c0 >> 1;

    int iy_base = (ty0 >> 1) - 1;
    int jx_base = (tx0 >> 1) - 1;

    float acc[8][4];
#pragma unroll
    for (int j = 0; j < 8; j++)
#pragma unroll
        for (int p = 0; p < 4; p++) acc[j][p] = 0.f;

    const float wscale = rsqrtf((float)(CIN * 9));
    const float* in_b = in + (size_t)b * CIN * HIN * HIN;

    for (int cb = 0; cb < CIN; cb += CI_T) {
        __syncthreads();
        for (int idx = tid; idx < CI_T * IR * ICW; idx += 256) {
            int ci = idx / (IR * ICW);
            int rem = idx % (IR * ICW);
            int iy = rem / ICW, ix = rem % ICW;
            int gy = iy_base + iy, gx = jx_base + ix;
            float v = 0.f;
            if (gy >= 0 && gy < HIN && gx >= 0 && gx < HIN)
                v = in_b[(size_t)(cb + ci) * HIN * HIN + gy * HIN + gx];
            s_in[ci][iy][ix] = v;
        }
        for (int idx = tid; idx < CO_T * CI_T * 9; idx += 256) {
            int co = idx / (CI_T * 9);
            int rem = idx % (CI_T * 9);
            int ci = rem / 9, tap = rem % 9;
            s_w[ci][tap][co] =
                wraw[((size_t)(co_base + co) * CIN + cb + ci) * 9 + tap] * wscale;
        }
        __syncthreads();
#pragma unroll
        for (int ci = 0; ci < CI_T; ci++) {
            int ky0 = r & 1;
            for (int ky = ky0; ky < 3; ky += 2) {
                int ir = ((r + ky - 2) >> 1) + 1;
                float x0v = s_in[ci][ir][h];
                float x1v = s_in[ci][ir][h + 1];
                float x2v = s_in[ci][ir][h + 2];
                int wr = (2 - ky) * 3;
#pragma unroll
                for (int j = 0; j < 8; j++) {
                    int co = co_grp * 8 + j;
                    float w0 = s_w[ci][wr + 0][co];
                    float w1 = s_w[ci][wr + 1][co];
                    float w2 = s_w[ci][wr + 2][co];
                    acc[j][0] = fmaf(w2, x0v, fmaf(w0, x1v, acc[j][0]));
                    acc[j][1] = fmaf(w1, x1v, acc[j][1]);
                    acc[j][2] = fmaf(w2, x1v, fmaf(w0, x2v, acc[j][2]));
                    acc[j][3] = fmaf(w1, x2v, acc[j][3]);
                }
            }
        }
    }
    int oy = ty0 + r;
    if (oy >= HOUT) return;
    float* out_b = out + (size_t)b * COUT * HOUT * HOUT;
#pragma unroll
    for (int j = 0; j < 8; j++) {
        int co = co_base + co_grp * 8 + j;
        float dm = demod[b * COUT + co];
#pragma unroll
        for (int p = 0; p < 4; p++) {
            int ox = tx0 + c0 + p;
            if (ox < HOUT)
                out_b[(size_t)co * HOUT * HOUT + oy * HOUT + ox] = acc[j][p] * dm;
        }
    }
}

// ---------------- 4x4 blur (pad 1, HIN -> HIN-1) + bias + leaky*sqrt2*style_next
template <int C, int HIN, bool SRC_A>
__global__ __launch_bounds__(256) void blur_kernel(const float* __restrict__ bias,
                                                   int style_id) {
    constexpr int HOUT = HIN - 1;
    constexpr int TH = 16, TW = 32;
    constexpr int TILES_X = HOUT / TW;
    __shared__ float s[TH + 3][TW + 4];

    const float* in = SRC_A ? g_bufA : g_bufB;
    float* out = SRC_A ? g_bufB : g_bufA;

    int tile = blockIdx.x;
    int x0 = (tile % TILES_X) * TW;
    int y0 = (tile / TILES_X) * TH;
    int c = blockIdx.y, b = blockIdx.z;
    const float* ip = in + ((size_t)b * C + c) * HIN * HIN;

    for (int idx = threadIdx.x; idx < (TH + 3) * (TW + 3); idx += 256) {
        int iy = idx / (TW + 3), ix = idx % (TW + 3);
        int gy = y0 + iy - 1, gx = x0 + ix - 1;
        float v = 0.f;
        if (gy >= 0 && gy < HIN && gx >= 0 && gx < HIN) v = ip[gy * HIN + gx];
        s[iy][ix] = v;
    }
    __syncthreads();

    const float c4[4] = {0.25f, 0.75f, 0.75f, 0.25f};
    float bi = bias[c];
    float sn = style_ptr(style_id)[b * C + c];
    float* op = out + ((size_t)b * C + c) * HOUT * HOUT;
#pragma unroll
    for (int q = 0; q < 2; q++) {
        int px = threadIdx.x + q * 256;
        int ly = px >> 5, lx = px & 31;
        float a = 0.f;
#pragma unroll
        for (int ky = 0; ky < 4; ky++) {
            float rs = 0.f;
#pragma unroll
            for (int kx = 0; kx < 4; kx++) rs += c4[kx] * s[ly + ky][lx + kx];
            a += c4[ky] * rs;
        }
        a += bi;
        a = (a > 0.f ? a : 0.2f * a) * 1.41421356237309515f * sn;
        op[(y0 + ly) * HOUT + x0 + lx] = a;
    }
}

// ---------------- final 1x1 (32 -> 3 of 4 ch), no demod, + out_bias ---------
__global__ void final_kernel(const float* __restrict__ finw,
                             const float* __restrict__ outb,
                             float* __restrict__ out) {
    int idx = blockIdx.x * blockDim.x + threadIdx.x;  // over 16*16384
    int b = idx >> 14;
    int p = idx & 16383;
    const float* ib = g_bufB + (size_t)b * 32 * 16384 + p;
    float a0 = 0.f, a1 = 0.f, a2 = 0.f;
#pragma unroll
    for (int ci = 0; ci < 32; ci++) {
        float v = ib[(size_t)ci * 16384];
        a0 = fmaf(finw[ci], v, a0);
        a1 = fmaf(finw[32 + ci], v, a1);
        a2 = fmaf(finw[64 + ci], v, a2);
    }
    const float sc = rsqrtf(32.0f);
    out[(size_t)b * 3 * 16384 + p] = a0 * sc + outb[0];
    out[(size_t)b * 3 * 16384 + 16384 + p] = a1 * sc + outb[1];
    out[(size_t)b * 3 * 16384 + 2 * 16384 + p] = a2 * sc + outb[2];
}

// ------------------------------------------------------------------------
extern "C" void kernel_launch(void* const* d_in, const int* in_sizes, int n_in,
                              void* d_out, int out_size) {
    (void)in_sizes; (void)n_in; (void)out_size;
    const float* fg = (const float*)d_in[0];
    const float* mask = (const float*)d_in[1];
    const float* bg = (const float*)d_in[2];
    const float* z = (const float*)d_in[3];
    const float* l_w[5]  = {(const float*)d_in[4],  (const float*)d_in[8],
                            (const float*)d_in[12], (const float*)d_in[16],
                            (const float*)d_in[20]};
    const float* l_mw[5] = {(const float*)d_in[5],  (const float*)d_in[9],
                            (const float*)d_in[13], (const float*)d_in[17],
                            (const float*)d_in[21]};
    const float* l_mb[5] = {(const float*)d_in[6],  (const float*)d_in[10],
                            (const float*)d_in[14], (const float*)d_in[18],
                            (const float*)d_in[22]};
    const float* l_b[5]  = {(const float*)d_in[7],  (const float*)d_in[11],
                            (const float*)d_in[15], (const float*)d_in[19],
                            (const float*)d_in[23]};
    const float* finw = (const float*)d_in[24];
    const float* fin_mw = (const float*)d_in[25];
    const float* fin_mb = (const float*)d_in[26];
    const float* outb = (const float*)d_in[27];

    const int Ci[6] = {256, 128, 128, 64, 64, 32};
    const int Co[5] = {128, 128, 64, 64, 32};

    // styles for all 6 modulated convs
    for (int l = 0; l < 6; l++) {
        const float* mw = (l < 5) ? l_mw[l] : fin_mw;
        const float* mb = (l < 5) ? l_mb[l] : fin_mb;
        int nwarp = NB * Ci[l];
        style_kernel<<<(nwarp + 7) / 8, 256>>>(z, mw, mb, Ci[l], l);
    }
    // per-layer sum-of-squared-weights, then demod factors
    for (int l = 0; l < 5; l++) {
        int n = Co[l] * Ci[l];
        wsq_kernel<<<(n + 255) / 256, 256>>>(l_w[l], Co[l], Ci[l], l);
    }
    for (int l = 0; l < 5; l++) {
        int nwarp = NB * Co[l];
        demod_kernel<<<(nwarp + 7) / 8, 256>>>(l, l, l, Co[l], Ci[l]);
    }

    // compose + modulate for layer 0 -> bufA
    compose_kernel<<<(NB * 256 * 1024) / 256, 256>>>(fg, mask, bg);

    // l0: 256->128 @32x32   (A -> B), epilogue styles for l1
    conv3x3_kernel<256, 128, 32, 32, true><<<dim3(4, 4, NB), 256>>>(l_w[0], l_b[0], 0, 1);
    // l1: tconv 128->128, 32 -> 65   (B -> A)
    tconv_kernel<128, 128, 32, false><<<dim3(27, 4, NB), 256>>>(l_w[1], 1);
    // blur 65 -> 64 + act + style2   (A -> B)
    blur_kernel<128, 65, true><<<dim3(8, 128, NB), 256>>>(l_b[1], 2);
    // l2: 128->64 @64x64   (B -> A), epilogue style3
    conv3x3_kernel<128, 64, 64, 64, false><<<dim3(16, 2, NB), 256>>>(l_w[2], l_b[2], 2, 3);
    // l3: tconv 64->64, 64 -> 129   (A -> B)
    tconv_kernel<64, 64, 64, true><<<dim3(85, 2, NB), 256>>>(l_w[3], 3);
    // blur 129 -> 128 + act + style4   (B -> A)
    blur_kernel<64, 129, false><<<dim3(32, 64, NB), 256>>>(l_b[3], 4);
    // l4: 64->32 @128x128   (A -> B), epilogue style_fin
    conv3x3_kernel<64, 32, 128, 128, true><<<dim3(64, 1, NB), 256>>>(l_w[4], l_b[4], 4, 5);
    // final 1x1 32->3 + out_bias   (B -> d_out)
    final_kernel<<<(NB * 16384) / 256, 256>>>(finw, outb, (float*)d_out);
}

// round 3
// speedup vs baseline: 1.0026x; 1.0026x over previous
#include <cuda_runtime.h>
#include <math.h>

#define NB 16
#define SDIM 512

typedef unsigned long long ull;

__device__ __forceinline__ ull pack2(float a, float b) {
    ull r;
    asm("mov.b64 %0, {%1, %2};" : "=l"(r) : "f"(a), "f"(b));
    return r;
}
__device__ __forceinline__ void unpack2(ull v, float& a, float& b) {
    asm("mov.b64 {%0, %1}, %2;" : "=f"(a), "=f"(b) : "l"(v));
}
__device__ __forceinline__ void ffma2(ull& d, ull a, ull b) {
    asm("fma.rn.f32x2 %0, %1, %2, %0;" : "+l"(d) : "l"(a), "l"(b));
}

// ---------------- persistent scratch (no allocs allowed) ----------------
static __device__ float g_bufA[16777216];   // max: (16,64,128,128)
static __device__ float g_bufB[17040384];   // max: (16,64,129,129)

static __device__ float g_style0[NB * 256];
static __device__ float g_style1[NB * 128];
static __device__ float g_style2[NB * 128];
static __device__ float g_style3[NB * 64];
static __device__ float g_style4[NB * 64];
static __device__ float g_stylef[NB * 32];

static __device__ float g_demod0[NB * 128];
static __device__ float g_demod1[NB * 128];
static __device__ float g_demod2[NB * 64];
static __device__ float g_demod3[NB * 64];
static __device__ float g_demod4[NB * 32];

static __device__ float g_wsq0[128 * 256];
static __device__ float g_wsq1[128 * 128];
static __device__ float g_wsq2[64 * 128];
static __device__ float g_wsq3[64 * 64];
static __device__ float g_wsq4[32 * 64];

__device__ __forceinline__ float* style_ptr(int id) {
    switch (id) {
        case 0: return g_style0;
        case 1: return g_style1;
        case 2: return g_style2;
        case 3: return g_style3;
        case 4: return g_style4;
        default: return g_stylef;
    }
}
__device__ __forceinline__ float* demod_ptr(int id) {
    switch (id) {
        case 0: return g_demod0;
        case 1: return g_demod1;
        case 2: return g_demod2;
        case 3: return g_demod3;
        default: return g_demod4;
    }
}
__device__ __forceinline__ float* wsq_ptr(int id) {
    switch (id) {
        case 0: return g_wsq0;
        case 1: return g_wsq1;
        case 2: return g_wsq2;
        case 3: return g_wsq3;
        default: return g_wsq4;
    }
}

// ---------------- style = z @ mw^T / sqrt(512) + mb ----------------
__global__ void style_kernel(const float* __restrict__ z,
                             const float* __restrict__ mw,
                             const float* __restrict__ mb,
                             int Ci, int style_id) {
    int warp = blockIdx.x * (blockDim.x >> 5) + (threadIdx.x >> 5);
    int lane = threadIdx.x & 31;
    if (warp >= NB * Ci) return;
    int b = warp / Ci;
    int ci = warp - b * Ci;
    const float* zr = z + b * SDIM;
    const float* mr = mw + (size_t)ci * SDIM;
    float s = 0.f;
#pragma unroll 4
    for (int k = lane; k < SDIM; k += 32) s += zr[k] * mr[k];
#pragma unroll
    for (int o = 16; o; o >>= 1) s += __shfl_xor_sync(0xffffffffu, s, o);
    if (lane == 0) style_ptr(style_id)[warp] = s * 0.04419417382415922f + mb[ci];
}

// ---------------- wsq[co,ci] = sum_taps (w^2) / (Ci*9) ----------------
__global__ void wsq_kernel(const float* __restrict__ w, int Co, int Ci, int wsq_id) {
    int i = blockIdx.x * blockDim.x + threadIdx.x;
    if (i >= Co * Ci) return;
    const float* p = w + (size_t)i * 9;
    float s = 0.f;
#pragma unroll
    for (int t = 0; t < 9; t++) s += p[t] * p[t];
    wsq_ptr(wsq_id)[i] = s * (1.0f / (float)(Ci * 9));
}

// ---------------- demod[b,co] = rsqrt(sum_ci style^2 * wsq + 1e-8) -----------
__global__ void demod_kernel(int style_id, int wsq_id, int demod_id, int Co, int Ci) {
    int warp = blockIdx.x * (blockDim.x >> 5) + (threadIdx.x >> 5);
    int lane = threadIdx.x & 31;
    if (warp >= NB * Co) return;
    int b = warp / Co;
    int co = warp - b * Co;
    const float* st = style_ptr(style_id) + b * Ci;
    const float* wq = wsq_ptr(wsq_id) + (size_t)co * Ci;
    float s = 0.f;
    for (int ci = lane; ci < Ci; ci += 32) {
        float sv = st[ci];
        s += sv * sv * wq[ci];
    }
#pragma unroll
    for (int o = 16; o; o >>= 1) s += __shfl_xor_sync(0xffffffffu, s, o);
    if (lane == 0) demod_ptr(demod_id)[warp] = rsqrtf(s + 1e-8f);
}

// ---------------- compose: bufA = (fg + (1-mask)*bg) * style0 ----------------
__global__ void compose_kernel(const float* __restrict__ fg,
                               const float* __restrict__ mask,
                               const float* __restrict__ bg) {
    int idx = blockIdx.x * blockDim.x + threadIdx.x;  // over 16*256*1024
    int p = idx & 1023;
    int c = (idx >> 10) & 255;
    int b = idx >> 18;
    float m = 1.0f - mask[b * 1024 + p];
    float v = fg[idx] + m * bg[idx];
    g_bufA[idx] = v * g_style0[b * 256 + c];
}

// ---------------- 3x3 conv, pad 1, f32x2-packed over co pairs ----------------
// Each warp: 4 consecutive co (2 f32x2 pairs); lane: r=lane>>2, c0=(lane&3)*8
// epilogue: v = acc*demod + bias; v = leaky(v)*sqrt2*style_next
template <int CIN, int COUT, int H, int W, bool SRC_A>
__global__ __launch_bounds__(256) void conv3x3_kernel(const float* __restrict__ wraw,
                                                      const float* __restrict__ bias,
                                                      int demod_id, int style_id) {
    constexpr int CO_T = 32, CI_T = 8, TH = 8, TW = 32;
    constexpr int IN_LD = 36;   // multiple of 4: float4-aligned rows
    constexpr int W_LD = 32;    // even: ull-aligned co pairs (broadcast reads)
    constexpr int TILES_X = W / TW;
    __shared__ __align__(16) float s_in[CI_T][TH + 2][IN_LD];
    __shared__ __align__(16) float s_w[CI_T][9][W_LD];

    const float* in = SRC_A ? g_bufA : g_bufB;
    float* out = SRC_A ? g_bufB : g_bufA;
    const float* demod = demod_ptr(demod_id);
    const float* styn = style_ptr(style_id);

    int tid = threadIdx.x;
    int tile = blockIdx.x;
    int tx0 = (tile % TILES_X) * TW;
    int ty0 = (tile / TILES_X) * TH;
    int co_base = blockIdx.y * CO_T;
    int b = blockIdx.z;

    int warp = tid >> 5;          // 0..7 -> co group of 4
    int lane = tid & 31;
    int r = lane >> 2;            // 0..7
    int c0 = (lane & 3) << 3;     // 0,8,16,24

    ull acc[2][8];
#pragma unroll
    for (int jp = 0; jp < 2; jp++)
#pragma unroll
        for (int p = 0; p < 8; p++) acc[jp][p] = 0ull;

    const float wscale = rsqrtf((float)(CIN * 9));
    const float* in_b = in + (size_t)b * CIN * H * W;

    for (int cb = 0; cb < CIN; cb += CI_T) {
        __syncthreads();
        // input tile (with halo), zero-padded at edges
        for (int idx = tid; idx < CI_T * (TH + 2) * 34; idx += 256) {
            int ci = idx / ((TH + 2) * 34);
            int rem = idx % ((TH + 2) * 34);
            int iy = rem / 34, ix = rem % 34;
            int gy = ty0 + iy - 1, gx = tx0 + ix - 1;
            float v = 0.f;
            if (gy >= 0 && gy < H && gx >= 0 && gx < W)
                v = in_b[(size_t)(cb + ci) * H * W + gy * W + gx];
            s_in[ci][iy][ix] = v;
        }
        // weights (pre-scaled)
        for (int idx = tid; idx < CO_T * CI_T * 9; idx += 256) {
            int co = idx / (CI_T * 9);
            int rem = idx % (CI_T * 9);
            int ci = rem / 9, tap = rem % 9;
            s_w[ci][tap][co] =
                wraw[((size_t)(co_base + co) * CIN + cb + ci) * 9 + tap] * wscale;
        }
        __syncthreads();
#pragma unroll
        for (int ci = 0; ci < CI_T; ci++) {
#pragma unroll
            for (int ky = 0; ky < 3; ky++) {
                const float4* row4 =
                    reinterpret_cast<const float4*>(&s_in[ci][r + ky][c0]);
                float4 q0 = row4[0];
                float4 q1 = row4[1];
                float4 q2 = row4[2];
                ull xd[10];
                xd[0] = pack2(q0.x, q0.x); xd[1] = pack2(q0.y, q0.y);
                xd[2] = pack2(q0.z, q0.z); xd[3] = pack2(q0.w, q0.w);
                xd[4] = pack2(q1.x, q1.x); xd[5] = pack2(q1.y, q1.y);
                xd[6] = pack2(q1.z, q1.z); xd[7] = pack2(q1.w, q1.w);
                xd[8] = pack2(q2.x, q2.x); xd[9] = pack2(q2.y, q2.y);
#pragma unroll
                for (int kx = 0; kx < 3; kx++) {
#pragma unroll
                    for (int jp = 0; jp < 2; jp++) {
                        ull w2 = *reinterpret_cast<const ull*>(
                            &s_w[ci][ky * 3 + kx][warp * 4 + jp * 2]);
#pragma unroll
                        for (int p = 0; p < 8; p++) ffma2(acc[jp][p], w2, xd[kx + p]);
                    }
                }
            }
        }
    }
    // epilogue
    int oy = ty0 + r;
    float* out_b = out + (size_t)b * COUT * H * W;
#pragma unroll
    for (int jp = 0; jp < 2; jp++) {
        float vlo[8], vhi[8];
#pragma unroll
        for (int p = 0; p < 8; p++) unpack2(acc[jp][p], vlo[p], vhi[p]);
#pragma unroll
        for (int h = 0; h < 2; h++) {
            int co = co_base + warp * 4 + jp * 2 + h;
            float dm = demod[b * COUT + co];
            float bi = bias[co];
            float sn = styn[b * COUT + co];
            float* op = out_b + (size_t)co * H * W + oy * W + tx0 + c0;
            const float* src = h ? vhi : vlo;
            float4 o0, o1;
            float t0, t1, t2, t3;
#pragma unroll
            for (int p = 0; p < 8; p++) {
                float v = src[p] * dm + bi;
                v = (v > 0.f ? v : 0.2f * v) * 1.41421356237309515f * sn;
                if (p == 0) t0 = v; else if (p == 1) t1 = v;
                else if (p == 2) t2 = v; else if (p == 3) t3 = v;
                else if (p == 4) o1.x = v; else if (p == 5) o1.y = v;
                else if (p == 6) o1.z = v; else o1.w = v;
            }
            o0.x = t0; o0.y = t1; o0.z = t2; o0.w = t3;
            reinterpret_cast<float4*>(op)[0] = o0;
            reinterpret_cast<float4*>(op)[1] = o1;
        }
    }
}

// ---------------- transposed conv (lhs_dilation=2, pad 2, flipped kernel) ----
// f32x2-packed over co pairs. out size = 2*HIN+1; epilogue: * demod only
template <int CIN, int COUT, int HIN, bool SRC_A>
__global__ __launch_bounds__(256) void tconv_kernel(const float* __restrict__ wraw,
                                                    int demod_id) {
    constexpr int HOUT = 2 * HIN + 1;
    constexpr int CO_T = 32, CI_T = 8, TH = 8, TW = 32;
    constexpr int IR = 6, ICW = 18, IC_LD = 19;
    constexpr int W_LD = 32;
    constexpr int TILES_X = (HOUT + TW - 1) / TW;
    __shared__ __align__(16) float s_in[CI_T][IR][IC_LD];
    __shared__ __align__(16) float s_w[CI_T][9][W_LD];

    const float* in = SRC_A ? g_bufA : g_bufB;
    float* out = SRC_A ? g_bufB : g_bufA;
    const float* demod = demod_ptr(demod_id);

    int tid = threadIdx.x;
    int tile = blockIdx.x;
    int tx0 = (tile % TILES_X) * TW;
    int ty0 = (tile / TILES_X) * TH;
    int co_base = blockIdx.y * CO_T;
    int b = blockIdx.z;

    int co_grp = tid >> 6;                      // 0..3 -> 8 co (4 pairs)
    int lane = tid & 31;
    int wrp = tid >> 5;
    int r = 2 * ((lane >> 3) & 3) + (wrp & 1);  // row parity uniform per warp
    int c0 = (lane & 7) << 2;
    int h = c0 >> 1;

    int iy_base = (ty0 >> 1) - 1;
    int jx_base = (tx0 >> 1) - 1;

    ull acc[4][4];
#pragma unroll
    for (int jp = 0; jp < 4; jp++)
#pragma unroll
        for (int p = 0; p < 4; p++) acc[jp][p] = 0ull;

    const float wscale = rsqrtf((float)(CIN * 9));
    const float* in_b = in + (size_t)b * CIN * HIN * HIN;

    for (int cb = 0; cb < CIN; cb += CI_T) {
        __syncthreads();
        for (int idx = tid; idx < CI_T * IR * ICW; idx += 256) {
            int ci = idx / (IR * ICW);
            int rem = idx % (IR * ICW);
            int iy = rem / ICW, ix = rem % ICW;
            int gy = iy_base + iy, gx = jx_base + ix;
            float v = 0.f;
            if (gy >= 0 && gy < HIN && gx >= 0 && gx < HIN)
                v = in_b[(size_t)(cb + ci) * HIN * HIN + gy * HIN + gx];
            s_in[ci][iy][ix] = v;
        }
        for (int idx = tid; idx < CO_T * CI_T * 9; idx += 256) {
            int co = idx / (CI_T * 9);
            int rem = idx % (CI_T * 9);
            int ci = rem / 9, tap = rem % 9;
            s_w[ci][tap][co] =
                wraw[((size_t)(co_base + co) * CIN + cb + ci) * 9 + tap] * wscale;
        }
        __syncthreads();
#pragma unroll
        for (int ci = 0; ci < CI_T; ci++) {
            int ky0 = r & 1;
            for (int ky = ky0; ky < 3; ky += 2) {
                int ir = ((r + ky - 2) >> 1) + 1;
                float x0v = s_in[ci][ir][h];
                float x1v = s_in[ci][ir][h + 1];
                float x2v = s_in[ci][ir][h + 2];
                ull xd0 = pack2(x0v, x0v);
                ull xd1 = pack2(x1v, x1v);
                ull xd2 = pack2(x2v, x2v);
                int wr = (2 - ky) * 3;
#pragma unroll
                for (int jp = 0; jp < 4; jp++) {
                    int co = co_grp * 8 + jp * 2;
                    ull w0 = *reinterpret_cast<const ull*>(&s_w[ci][wr + 0][co]);
                    ull w1 = *reinterpret_cast<const ull*>(&s_w[ci][wr + 1][co]);
                    ull w2 = *reinterpret_cast<const ull*>(&s_w[ci][wr + 2][co]);
                    ffma2(acc[jp][0], w2, xd0);
                    ffma2(acc[jp][0], w0, xd1);
                    ffma2(acc[jp][1], w1, xd1);
                    ffma2(acc[jp][2], w2, xd1);
                    ffma2(acc[jp][2], w0, xd2);
                    ffma2(acc[jp][3], w1, xd2);
                }
            }
        }
    }
    int oy = ty0 + r;
    if (oy >= HOUT) return;
    float* out_b = out + (size_t)b * COUT * HOUT * HOUT;
#pragma unroll
    for (int jp = 0; jp < 4; jp++) {
#pragma unroll
        for (int hh = 0; hh < 2; hh++) {
            int co = co_base + co_grp * 8 + jp * 2 + hh;
            float dm = demod[b * COUT + co];
#pragma unroll
            for (int p = 0; p < 4; p++) {
                float lo, hi;
                unpack2(acc[jp][p], lo, hi);
                float v = (hh ? hi : lo) * dm;
                int ox = tx0 + c0 + p;
                if (ox < HOUT)
                    out_b[(size_t)co * HOUT * HOUT + oy * HOUT + ox] = v;
            }
        }
    }
}

// ---------------- 4x4 blur (pad 1, HIN -> HIN-1) + bias + leaky*sqrt2*style_next
template <int C, int HIN, bool SRC_A>
__global__ __launch_bounds__(256) void blur_kernel(const float* __restrict__ bias,
                                                   int style_id) {
    constexpr int HOUT = HIN - 1;
    constexpr int TH = 16, TW = 32;
    constexpr int TILES_X = HOUT / TW;
    __shared__ float s[TH + 3][TW + 4];

    const float* in = SRC_A ? g_bufA : g_bufB;
    float* out = SRC_A ? g_bufB : g_bufA;

    int tile = blockIdx.x;
    int x0 = (tile % TILES_X) * TW;
    int y0 = (tile / TILES_X) * TH;
    int c = blockIdx.y, b = blockIdx.z;
    const float* ip = in + ((size_t)b * C + c) * HIN * HIN;

    for (int idx = threadIdx.x; idx < (TH + 3) * (TW + 3); idx += 256) {
        int iy = idx / (TW + 3), ix = idx % (TW + 3);
        int gy = y0 + iy - 1, gx = x0 + ix - 1;
        float v = 0.f;
        if (gy >= 0 && gy < HIN && gx >= 0 && gx < HIN) v = ip[gy * HIN + gx];
        s[iy][ix] = v;
    }
    __syncthreads();

    const float c4[4] = {0.25f, 0.75f, 0.75f, 0.25f};
    float bi = bias[c];
    float sn = style_ptr(style_id)[b * C + c];
    float* op = out + ((size_t)b * C + c) * HOUT * HOUT;
#pragma unroll
    for (int q = 0; q < 2; q++) {
        int px = threadIdx.x + q * 256;
        int ly = px >> 5, lx = px & 31;
        float a = 0.f;
#pragma unroll
        for (int ky = 0; ky < 4; ky++) {
            float rs = 0.f;
#pragma unroll
            for (int kx = 0; kx < 4; kx++) rs += c4[kx] * s[ly + ky][lx + kx];
            a += c4[ky] * rs;
        }
        a += bi;
        a = (a > 0.f ? a : 0.2f * a) * 1.41421356237309515f * sn;
        op[(y0 + ly) * HOUT + x0 + lx] = a;
    }
}

// ---------------- final 1x1 (32 -> 3 of 4 ch), no demod, + out_bias ---------
__global__ void final_kernel(const float* __restrict__ finw,
                             const float* __restrict__ outb,
                             float* __restrict__ out) {
    int idx = blockIdx.x * blockDim.x + threadIdx.x;  // over 16*16384
    int b = idx >> 14;
    int p = idx & 16383;
    const float* ib = g_bufB + (size_t)b * 32 * 16384 + p;
    float a0 = 0.f, a1 = 0.f, a2 = 0.f;
#pragma unroll
    for (int ci = 0; ci < 32; ci++) {
        float v = ib[(size_t)ci * 16384];
        a0 = fmaf(finw[ci], v, a0);
        a1 = fmaf(finw[32 + ci], v, a1);
        a2 = fmaf(finw[64 + ci], v, a2);
    }
    const float sc = rsqrtf(32.0f);
    out[(size_t)b * 3 * 16384 + p] = a0 * sc + outb[0];
    out[(size_t)b * 3 * 16384 + 16384 + p] = a1 * sc + outb[1];
    out[(size_t)b * 3 * 16384 + 2 * 16384 + p] = a2 * sc + outb[2];
}

// ------------------------------------------------------------------------
extern "C" void kernel_launch(void* const* d_in, const int* in_sizes, int n_in,
                              void* d_out, int out_size) {
    (void)in_sizes; (void)n_in; (void)out_size;
    const float* fg = (const float*)d_in[0];
    const float* mask = (const float*)d_in[1];
    const float* bg = (const float*)d_in[2];
    const float* z = (const float*)d_in[3];
    const float* l_w[5]  = {(const float*)d_in[4],  (const float*)d_in[8],
                            (const float*)d_in[12], (const float*)d_in[16],
                            (const float*)d_in[20]};
    const float* l_mw[5] = {(const float*)d_in[5],  (const float*)d_in[9],
                            (const float*)d_in[13], (const float*)d_in[17],
                            (const float*)d_in[21]};
    const float* l_mb[5] = {(const float*)d_in[6],  (const float*)d_in[10],
                            (const float*)d_in[14], (const float*)d_in[18],
                            (const float*)d_in[22]};
    const float* l_b[5]  = {(const float*)d_in[7],  (const float*)d_in[11],
                            (const float*)d_in[15], (const float*)d_in[19],
                            (const float*)d_in[23]};
    const float* finw = (const float*)d_in[24];
    const float* fin_mw = (const float*)d_in[25];
    const float* fin_mb = (const float*)d_in[26];
    const float* outb = (const float*)d_in[27];

    const int Ci[6] = {256, 128, 128, 64, 64, 32};
    const int Co[5] = {128, 128, 64, 64, 32};

    // styles for all 6 modulated convs
    for (int l = 0; l < 6; l++) {
        const float* mw = (l < 5) ? l_mw[l] : fin_mw;
        const float* mb = (l < 5) ? l_mb[l] : fin_mb;
        int nwarp = NB * Ci[l];
        style_kernel<<<(nwarp + 7) / 8, 256>>>(z, mw, mb, Ci[l], l);
    }
    // per-layer sum-of-squared-weights, then demod factors
    for (int l = 0; l < 5; l++) {
        int n = Co[l] * Ci[l];
        wsq_kernel<<<(n + 255) / 256, 256>>>(l_w[l], Co[l], Ci[l], l);
    }
    for (int l = 0; l < 5; l++) {
        int nwarp = NB * Co[l];
        demod_kernel<<<(nwarp + 7) / 8, 256>>>(l, l, l, Co[l], Ci[l]);
    }

    // compose + modulate for layer 0 -> bufA
    compose_kernel<<<(NB * 256 * 1024) / 256, 256>>>(fg, mask, bg);

    // l0: 256->128 @32x32   (A -> B), epilogue styles for l1
    conv3x3_kernel<256, 128, 32, 32, true><<<dim3(4, 4, NB), 256>>>(l_w[0], l_b[0], 0, 1);
    // l1: tconv 128->128, 32 -> 65   (B -> A)
    tconv_kernel<128, 128, 32, false><<<dim3(27, 4, NB), 256>>>(l_w[1], 1);
    // blur 65 -> 64 + act + style2   (A -> B)
    blur_kernel<128, 65, true><<<dim3(8, 128, NB), 256>>>(l_b[1], 2);
    // l2: 128->64 @64x64   (B -> A), epilogue style3
    conv3x3_kernel<128, 64, 64, 64, false><<<dim3(16, 2, NB), 256>>>(l_w[2], l_b[2], 2, 3);
    // l3: tconv 64->64, 64 -> 129   (A -> B)
    tconv_kernel<64, 64, 64, true><<<dim3(85, 2, NB), 256>>>(l_w[3], 3);
    // blur 129 -> 128 + act + style4   (B -> A)
    blur_kernel<64, 129, false><<<dim3(32, 64, NB), 256>>>(l_b[3], 4);
    // l4: 64->32 @128x128   (A -> B), epilogue style_fin
    conv3x3_kernel<64, 32, 128, 128, true><<<dim3(64, 1, NB), 256>>>(l_w[4], l_b[4], 4, 5);
    // final 1x1 32->3 + out_bias   (B -> d_out)
    final_kernel<<<(NB * 16384) / 256, 256>>>(finw, outb, (float*)d_out);
}